// round 12
// baseline (speedup 1.0000x reference)
#include <cuda_runtime.h>
#include <cuda_bf16.h>

#define TT 2048
#define BB 4096
#define NTH 128
#define NCTA 128

typedef unsigned long long u64;
typedef unsigned int u32;
typedef unsigned short u16;

static __device__ __forceinline__ u64 pk2(float x, float y){
    u64 r; asm("mov.b64 %0,{%1,%2};" : "=l"(r) : "f"(x), "f"(y)); return r;
}
static __device__ __forceinline__ void up2(u64 v, float &x, float &y){
    asm("mov.b64 {%0,%1},%2;" : "=f"(x), "=f"(y) : "l"(v));
}
static __device__ __forceinline__ u64 add2(u64 a, u64 b){
    u64 d; asm("add.rn.f32x2 %0,%1,%2;" : "=l"(d) : "l"(a), "l"(b)); return d;
}
static __device__ __forceinline__ float pick4(float a, float b, float c, float d, int s){
    float x = (s & 1) ? b : a;
    float y = (s & 1) ? d : c;
    return (s & 2) ? y : x;
}
static __device__ __forceinline__ float pick8(float a0, float a1, float a2, float a3,
                                              float a4, float a5, float a6, float a7, int s){
    float x = pick4(a0, a1, a2, a3, s & 3);
    float y = pick4(a4, a5, a6, a7, s & 3);
    return (s & 4) ? y : x;
}
static __device__ __forceinline__ u32 bfpack(float lo, float hi){
    u32 r; asm("cvt.rn.bf16x2.f32 %0, %1, %2;" : "=r"(r) : "f"(hi), "f"(lo)); return r;
}
static __device__ __forceinline__ u16 bf1(float x){
    __nv_bfloat16 b = __float2bfloat16(x);
    return *reinterpret_cast<u16*>(&b);
}
// D(16x8,f32) += A(16x16,bf16 row) * B(16x8,bf16 col)
static __device__ __forceinline__ void mma16816(
    float &c0, float &c1, float &c2, float &c3,
    u32 a0, u32 a1, u32 a2, u32 a3, u32 b0, u32 b1)
{
    asm("mma.sync.aligned.m16n8k16.row.col.f32.bf16.bf16.f32 "
        "{%0,%1,%2,%3},{%4,%5,%6,%7},{%8,%9},{%0,%1,%2,%3};"
        : "+f"(c0), "+f"(c1), "+f"(c2), "+f"(c3)
        : "r"(a0), "r"(a1), "r"(a2), "r"(a3), "r"(b0), "r"(b1));
}

__global__ __launch_bounds__(NTH, 1)
void garch_pinn_kernel(
    const float* __restrict__ returns, const float* __restrict__ log_rv,
    const float* __restrict__ omega_p, const float* __restrict__ beta_p,
    const float* __restrict__ tau1_p, const float* __restrict__ tau2_p,
    const float* __restrict__ gamma_p, const float* __restrict__ xi_p,
    const float* __restrict__ phi_p, const float* __restrict__ d1_p,
    const float* __restrict__ d2_p, const float* __restrict__ mu_p,
    const float* __restrict__ W1, const float* __restrict__ b1,
    const float* __restrict__ W2, const float* __restrict__ b2,
    const float* __restrict__ W3, const float* __restrict__ b3_p,
    float* __restrict__ out)
{
    // bf16 h tile per warp: [chain 0..7][i 0..63 pad 72]
    // bank(chain,k,kt) = (4*chain + k/2 + 8*kt) mod 32 -> all lanes distinct
    __shared__ u16 hsm[4][8][72];                    // 4.6 KB
    // per-warp output staging: [warp][arr*8+chain][33]
    __shared__ float obuf[4][32][33];                // 16.9 KB

    const int tid = threadIdx.x;
    const int w = tid >> 5;
    const int l = tid & 31;
    const int r = l >> 2;          // mma row group / b-chain
    const int kq = (l & 3) * 2;    // mma k / col pair base

    // ---- A fragments (A[m][k] = W2[k][m]) preloaded, 4 mt x 4 kt x 4 regs ----
    u32 afr[4][4][4];
    #pragma unroll
    for (int mt = 0; mt < 4; mt++) {
        #pragma unroll
        for (int kt = 0; kt < 4; kt++) {
            const int m0 = 16 * mt + r, k0 = 16 * kt + kq;
            afr[mt][kt][0] = bfpack(W2[k0 * 64 + m0],           W2[(k0 + 1) * 64 + m0]);
            afr[mt][kt][1] = bfpack(W2[k0 * 64 + m0 + 8],       W2[(k0 + 1) * 64 + m0 + 8]);
            afr[mt][kt][2] = bfpack(W2[(k0 + 8) * 64 + m0],     W2[(k0 + 9) * 64 + m0]);
            afr[mt][kt][3] = bfpack(W2[(k0 + 8) * 64 + m0 + 8], W2[(k0 + 9) * 64 + m0 + 8]);
        }
    }
    // epilogue row constants
    float b2lo[4], b2hi[4], w3lo[4], w3hi[4];
    #pragma unroll
    for (int mt = 0; mt < 4; mt++) {
        b2lo[mt] = b2[16 * mt + r];     b2hi[mt] = b2[16 * mt + r + 8];
        w3lo[mt] = W3[16 * mt + r];     w3hi[mt] = W3[16 * mt + r + 8];
    }

    // layer-1 constants: lane computes h1 rows l and l+32
    const float w1a0 = W1[0 * 64 + l],      w1a1 = W1[1 * 64 + l],      w1a2 = W1[2 * 64 + l];
    const float w1b0 = W1[0 * 64 + l + 32], w1b1 = W1[1 * 64 + l + 32], w1b2 = W1[2 * 64 + l + 32];
    const float b1a = b1[l], b1b = b1[l + 32];

    const float omega = *omega_p, beta = *beta_p, tau1 = *tau1_p, tau2 = *tau2_p;
    const float gam = *gamma_p, xi = *xi_p, phi = *phi_p;
    const float d1 = *d1_p, d2 = *d2_p, mu = *mu_p, b3 = *b3_p;

    // this warp's 8 batch chains
    const long bg = (long)blockIdx.x * 32 + w * 8;
    const float* rp = returns + bg * TT;
    const float* lp = log_rv + bg * TT;
    const long BT = (long)BB * TT;

    float lh[8];
    #pragma unroll
    for (int b = 0; b < 8; b++) lh[b] = lp[b * TT];   // log(mean(exp(lrv0))) == lrv0

    u16* hw = &hsm[w][0][0];
    const u16* browp = &hsm[w][r][kq];   // b-chain r, k-pair kq
    float* obw = &obuf[w][0][0];

    for (int t = 0; t < TT; t++) {
        // ---- inputs (warp-uniform) ----
        float rcur[8], lcur[8];
        #pragma unroll
        for (int b = 0; b < 8; b++) { rcur[b] = rp[b * TT + t]; lcur[b] = lp[b * TT + t]; }

        // ---- measurement (exact fp32, all lanes) ----
        float z[8], u[8], z2m1[8];
        #pragma unroll
        for (int b = 0; b < 8; b++) {
            float e = __expf(-0.5f * lh[b]);
            z[b] = (rcur[b] - mu) * e;
            z2m1[b] = z[b] * z[b] - 1.0f;
            float s = xi + phi * lh[b] + d1 * z[b] + d2 * z2m1[b];
            u[b] = lcur[b] - s;              // log_x == lcur exactly
        }

        // ---- layer 1 (fp32): rows l and l+32, 8 chains; store bf16 tile ----
        #pragma unroll
        for (int b = 0; b < 8; b++) {
            float t0 = fmaf(w1a0, lh[b], b1a);
            t0 = fmaf(w1a1, z[b], t0);
            t0 = fmaf(w1a2, u[b], t0);
            hw[b * 72 + l] = bf1(fmaxf(t0, 0.0f));
            float t1 = fmaf(w1b0, lh[b], b1b);
            t1 = fmaf(w1b1, z[b], t1);
            t1 = fmaf(w1b2, u[b], t1);
            hw[b * 72 + l + 32] = bf1(fmaxf(t1, 0.0f));
        }

        // stage reduction-independent outputs: lanes 8..31 -> arr 1=lx,2=z,3=u
        if (l >= 8) {
            const int ch = l & 7;
            float v_lx = pick8(lcur[0], lcur[1], lcur[2], lcur[3],
                               lcur[4], lcur[5], lcur[6], lcur[7], ch);
            float v_z  = pick8(z[0], z[1], z[2], z[3], z[4], z[5], z[6], z[7], ch);
            float v_u  = pick8(u[0], u[1], u[2], u[3], u[4], u[5], u[6], u[7], ch);
            float v = (l >= 24) ? v_u : (l >= 16) ? v_z : v_lx;
            obw[l * 33 + (t & 31)] = v;
        }
        __syncwarp();

        // ---- B fragments: lane -> chain r, k-pairs (kq,kq+1) and (+8,+9) ----
        u32 bfr[4][2];
        #pragma unroll
        for (int kt = 0; kt < 4; kt++) {
            bfr[kt][0] = *reinterpret_cast<const u32*>(browp + 16 * kt);
            bfr[kt][1] = *reinterpret_cast<const u32*>(browp + 16 * kt + 8);
        }

        // ---- layer 2 on tensor pipe: y = W2^T h + b2 (full N=8) ----
        float cf[4][4];
        #pragma unroll
        for (int mt = 0; mt < 4; mt++) {
            cf[mt][0] = b2lo[mt]; cf[mt][1] = b2lo[mt];
            cf[mt][2] = b2hi[mt]; cf[mt][3] = b2hi[mt];
            #pragma unroll
            for (int kt = 0; kt < 4; kt++)
                mma16816(cf[mt][0], cf[mt][1], cf[mt][2], cf[mt][3],
                         afr[mt][kt][0], afr[mt][kt][1], afr[mt][kt][2], afr[mt][kt][3],
                         bfr[kt][0], bfr[kt][1]);
        }

        // ---- layer 3 epilogue: relu + W3 dot; lane holds chains (kq, kq+1) ----
        float pe = 0.0f, po = 0.0f;
        #pragma unroll
        for (int mt = 0; mt < 4; mt++) {
            pe = fmaf(fmaxf(cf[mt][0], 0.0f), w3lo[mt], pe);
            pe = fmaf(fmaxf(cf[mt][2], 0.0f), w3hi[mt], pe);
            po = fmaf(fmaxf(cf[mt][1], 0.0f), w3lo[mt], po);
            po = fmaf(fmaxf(cf[mt][3], 0.0f), w3hi[mt], po);
        }
        u64 pair = pk2(pe, po);
        // reduce over row groups: lanes with equal (l&3) hold same chain pair
        #pragma unroll
        for (int s = 4; s <= 16; s <<= 1)
            pair = add2(pair, __shfl_xor_sync(0xffffffffu, pair, s));
        // broadcast all 4 chain pairs from lane class base..base+3
        const int base = l & ~3;
        float tot[8];
        #pragma unroll
        for (int j = 0; j < 4; j++) {
            u64 tp = __shfl_sync(0xffffffffu, pair, base + j);
            up2(tp, tot[2 * j], tot[2 * j + 1]);
        }

        float enh[8];
        #pragma unroll
        for (int b = 0; b < 8; b++)
            enh[b] = fmaf(0.01f, tot[b] + b3, lh[b]);

        // stage enh (lanes 0..7)
        if (l < 8)
            obw[l * 33 + (t & 31)] = pick8(enh[0], enh[1], enh[2], enh[3],
                                           enh[4], enh[5], enh[6], enh[7], l);

        // ---- GARCH recurrence ----
        #pragma unroll
        for (int b = 0; b < 8; b++) {
            float nl = fmaf(beta, enh[b], omega);
            nl = fmaf(tau1, z[b], nl);
            nl = fmaf(tau2, z2m1[b], nl);
            lh[b] = fmaf(gam, u[b], nl);
        }

        // ---- coalesced flush every 32 steps ----
        if ((t & 31) == 31) {
            const int t0 = t - 31;
            #pragma unroll
            for (int q = 0; q < 32; q++) {
                const int arr = q >> 3, ch = q & 7;
                out[(long)arr * BT + (bg + ch) * TT + t0 + l] = obw[q * 33 + l];
            }
        }
        __syncwarp();
    }
}

extern "C" void kernel_launch(void* const* d_in, const int* in_sizes, int n_in,
                              void* d_out, int out_size)
{
    garch_pinn_kernel<<<NCTA, NTH>>>(
        (const float*)d_in[0],  (const float*)d_in[1],
        (const float*)d_in[2],  (const float*)d_in[3],
        (const float*)d_in[4],  (const float*)d_in[5],
        (const float*)d_in[6],  (const float*)d_in[7],
        (const float*)d_in[8],  (const float*)d_in[9],
        (const float*)d_in[10], (const float*)d_in[11],
        (const float*)d_in[12], (const float*)d_in[13],
        (const float*)d_in[14], (const float*)d_in[15],
        (const float*)d_in[16], (const float*)d_in[17],
        (float*)d_out);
}